// round 1
// baseline (speedup 1.0000x reference)
#include <cuda_runtime.h>
#include <cstdint>

// Problem constants (shapes fixed by the reference)
#define KV_LEN      4096
#define PAGE_SZ     16
#define BSZ         4
#define SEQ         512
#define HEADS       16
#define HDIM        128
#define PAGES       1024
#define PPS         256     // pages per sequence
// SHIFT(16) + SEQ(512) = 528 = 33 pages
#define SHIFT_PAGES 33
#define FIRST_NEW_PAGE 223  // 3568/16: first page sourced from fresh k/v
#define LAST_PAGE   255     // page that keeps its own old content

// float4 geometry
#define HALF_F4  8192       // one kv half of a page: 16*16*128/4
#define PAGE_F4  16384      // full page (k + v halves)
#define SLOT_F4  512        // one slot (token): 16*128/4
#define HEAD_F4  32         // one head: 128/4

// log2(10000)/64
#define LOG2_THETA_OVER_64 0.2076205059304601486

__global__ __launch_bounds__(256, 8) void kv_rotate_kernel(
    const float* __restrict__ knew,
    const float* __restrict__ vnew,
    const float* __restrict__ cache,
    const int*   __restrict__ pidx,
    float*       __restrict__ out)
{
    const int i   = blockIdx.x;   // logical page 0..1023
    const int kv  = blockIdx.y;   // 0 = k half (rope), 1 = v half (copy)
    const int b   = i >> 8;
    const int p   = i & 255;
    const int tid = threadIdx.x;

    // destination page (scatter through the index array)
    const int dpage = pidx[i];
    float4* dst = (float4*)out + (size_t)dpage * PAGE_F4 + kv * HALF_F4;

    // source selection (page-granular thanks to SHIFT+SEQ being a multiple of PAGE_SZ)
    const float4* src;
    if (p < FIRST_NEW_PAGE) {
        const int spage = pidx[b * PPS + p + SHIFT_PAGES];
        src = (const float4*)cache + (size_t)spage * PAGE_F4 + kv * HALF_F4;
    } else if (p == LAST_PAGE) {
        src = (const float4*)cache + (size_t)dpage * PAGE_F4 + kv * HALF_F4;
    } else {
        const float* base = kv ? vnew : knew;
        // fresh rows: token row b*512 + (p-223)*16, 16 contiguous rows of HEADS*HDIM
        src = (const float4*)base
            + (size_t)(b * SEQ + (p - FIRST_NEW_PAGE) * PAGE_SZ) * (HEADS * HDIM / 4);
    }

    if (kv == 1) {
        // v half: straight 128KB streaming copy
        #pragma unroll 4
        for (int u = tid; u < HALF_F4; u += 256) {
            float4 x = __ldcs(&src[u]);
            __stcs(&dst[u], x);
        }
        return;
    }

    // ---- k half: rotate-half RoPE ----
    __shared__ float s_if[64];
    __shared__ float s_cos[16][64];
    __shared__ float s_sin[16][64];

    if (tid < 64) {
        // inv_freq in double, rounded to fp32 (matches jnp within ~1 ulp)
        s_if[tid] = (float)exp2(-(double)tid * LOG2_THETA_OVER_64);
    }
    __syncthreads();

    const int tbase = p * PAGE_SZ;
    for (int u = tid; u < 16 * 64; u += 256) {
        const int slot = u >> 6;
        const int f    = u & 63;
        const float ang = (float)(tbase + slot) * s_if[f];   // fp32 angle like the reference
        float s, c;
        sincosf(ang, &s, &c);
        s_cos[slot][f] = c;
        s_sin[slot][f] = s;
    }
    __syncthreads();

    // 16 slots * 16 heads * 16 float4-pairs = 4096 work units
    #pragma unroll 2
    for (int u = tid; u < 16 * HEADS * 16; u += 256) {
        const int slot = u >> 8;
        const int rem  = u & 255;
        const int h    = rem >> 4;
        const int j    = rem & 15;   // covers dims 4j..4j+3 (first half) and +64 (second half)

        const float4* sp = src + slot * SLOT_F4 + h * HEAD_F4 + j;
        const float4 a  = __ldcs(&sp[0]);    // x1 = x[d]
        const float4 bb = __ldcs(&sp[16]);   // x2 = x[d+64]

        const float4 c = *(const float4*)&s_cos[slot][4 * j];
        const float4 s = *(const float4*)&s_sin[slot][4 * j];

        float4 o1, o2;
        o1.x = a.x * c.x - bb.x * s.x;  o2.x = a.x * s.x + bb.x * c.x;
        o1.y = a.y * c.y - bb.y * s.y;  o2.y = a.y * s.y + bb.y * c.y;
        o1.z = a.z * c.z - bb.z * s.z;  o2.z = a.z * s.z + bb.z * c.z;
        o1.w = a.w * c.w - bb.w * s.w;  o2.w = a.w * s.w + bb.w * c.w;

        float4* dp = dst + slot * SLOT_F4 + h * HEAD_F4 + j;
        __stcs(&dp[0],  o1);
        __stcs(&dp[16], o2);
    }
}

extern "C" void kernel_launch(void* const* d_in, const int* in_sizes, int n_in,
                              void* d_out, int out_size) {
    const float* k     = (const float*)d_in[0];
    const float* v     = (const float*)d_in[1];
    const float* cache = (const float*)d_in[2];
    const int*   pidx  = (const int*)d_in[3];
    float*       out   = (float*)d_out;

    dim3 grid(PAGES, 2);
    kv_rotate_kernel<<<grid, 256>>>(k, v, cache, pidx, out);
}

// round 3
// speedup vs baseline: 1.0712x; 1.0712x over previous
#include <cuda_runtime.h>
#include <cstdint>

// Problem constants
#define KV_LEN      4096
#define PAGE_SZ     16
#define BSZ         4
#define SEQ         512
#define HEADS       16
#define HDIM        128
#define PAGES       1024
#define PPS         256
#define SHIFT_PAGES 33
#define FIRST_NEW_PAGE 223
#define LAST_PAGE   255

// float4 geometry
#define HALF_F4  8192       // one kv half of a page
#define PAGE_F4  16384
#define SLOT_F4  512        // one token: 16*128/4
#define HEAD_F4  32
#define CHUNK_F4 2048       // quarter of a half: 4 slots

// log2(10000)/64
#define LOG2_THETA_OVER_64 0.2076205059304601486

// Task decomposition: 8192 tasks of 32KB each.
//   kv    = t & 1        (interleave rope/copy across SMs)
//   chunk = (t>>1) & 3   (quarter within the half: 4 slots)
//   i     = t >> 3       (logical page 0..1023)
__global__ __launch_bounds__(256) void kv_rotate_kernel(
    const float* __restrict__ knew,
    const float* __restrict__ vnew,
    const float* __restrict__ cache,
    const int*   __restrict__ pidx,
    float*       __restrict__ out)
{
    const int t     = blockIdx.x;
    const int kv    = t & 1;
    const int chunk = (t >> 1) & 3;
    const int i     = t >> 3;
    const int b     = i >> 8;
    const int p     = i & 255;
    const int tid   = threadIdx.x;

    const int dpage = __ldg(&pidx[i]);
    float4* dst = (float4*)out + (size_t)dpage * PAGE_F4 + kv * HALF_F4 + chunk * CHUNK_F4;

    // source selection (page-granular: SHIFT+SEQ = 33 pages)
    const float4* src;
    if (p < FIRST_NEW_PAGE) {
        const int spage = __ldg(&pidx[b * PPS + p + SHIFT_PAGES]);
        src = (const float4*)cache + (size_t)spage * PAGE_F4 + kv * HALF_F4 + chunk * CHUNK_F4;
    } else if (p == LAST_PAGE) {
        src = (const float4*)cache + (size_t)dpage * PAGE_F4 + kv * HALF_F4 + chunk * CHUNK_F4;
    } else {
        const float* base = kv ? vnew : knew;
        src = (const float4*)base
            + (size_t)(b * SEQ + (p - FIRST_NEW_PAGE) * PAGE_SZ) * SLOT_F4 + chunk * CHUNK_F4;
    }

    if (kv == 1) {
        // pure streaming copy: 2048 f4, front-batched MLP=8
        float4 r[8];
        #pragma unroll
        for (int j = 0; j < 8; j++) r[j] = __ldcs(&src[tid + 256 * j]);
        #pragma unroll
        for (int j = 0; j < 8; j++) __stcs(&dst[tid + 256 * j], r[j]);
        return;
    }

    // ---- k quarter: rotate-half RoPE on 4 slots ----
    __shared__ float s_cos[4][64];
    __shared__ float s_sin[4][64];

    {
        // 4 slots * 64 freqs = 256 entries: exactly one per thread
        const int slot = tid >> 6;
        const int f    = tid & 63;
        const float invf = (float)exp2(-(double)f * LOG2_THETA_OVER_64);  // f32-rounded inv_freq
        const float ang  = (float)(p * PAGE_SZ + chunk * 4 + slot) * invf;
        float s, c;
        sincosf(ang, &s, &c);
        s_cos[slot][f] = c;
        s_sin[slot][f] = s;
    }
    __syncthreads();

    // 4 slots * 16 heads * 16 j-chunks = 1024 units, 4 per thread; slot == iter
    const int h = tid >> 4;
    const int j = tid & 15;
    const int lane_off = h * HEAD_F4 + j;

    float4 a[4], bb[4];
    #pragma unroll
    for (int it = 0; it < 4; it++) {
        const float4* sp = src + it * SLOT_F4 + lane_off;
        a[it]  = __ldcs(&sp[0]);    // x1 (dims 4j..4j+3)
        bb[it] = __ldcs(&sp[16]);   // x2 (dims 64+4j..)
    }

    const float4 cj[4] = { *(const float4*)&s_cos[0][4 * j], *(const float4*)&s_cos[1][4 * j],
                           *(const float4*)&s_cos[2][4 * j], *(const float4*)&s_cos[3][4 * j] };
    const float4 sj[4] = { *(const float4*)&s_sin[0][4 * j], *(const float4*)&s_sin[1][4 * j],
                           *(const float4*)&s_sin[2][4 * j], *(const float4*)&s_sin[3][4 * j] };

    #pragma unroll
    for (int it = 0; it < 4; it++) {
        float4 o1, o2;
        o1.x = a[it].x * cj[it].x - bb[it].x * sj[it].x;  o2.x = a[it].x * sj[it].x + bb[it].x * cj[it].x;
        o1.y = a[it].y * cj[it].y - bb[it].y * sj[it].y;  o2.y = a[it].y * sj[it].y + bb[it].y * cj[it].y;
        o1.z = a[it].z * cj[it].z - bb[it].z * sj[it].z;  o2.z = a[it].z * sj[it].z + bb[it].z * cj[it].z;
        o1.w = a[it].w * cj[it].w - bb[it].w * sj[it].w;  o2.w = a[it].w * sj[it].w + bb[it].w * cj[it].w;

        float4* dp = dst + it * SLOT_F4 + lane_off;
        __stcs(&dp[0],  o1);
        __stcs(&dp[16], o2);
    }
}

extern "C" void kernel_launch(void* const* d_in, const int* in_sizes, int n_in,
                              void* d_out, int out_size) {
    const float* k     = (const float*)d_in[0];
    const float* v     = (const float*)d_in[1];
    const float* cache = (const float*)d_in[2];
    const int*   pidx  = (const int*)d_in[3];
    float*       out   = (float*)d_out;

    kv_rotate_kernel<<<PAGES * 8, 256>>>(k, v, cache, pidx, out);
}